// round 12
// baseline (speedup 1.0000x reference)
#include <cuda_runtime.h>
#include <cuda_bf16.h>
#include <cstdint>
#include <math.h>

#define N_ROWS 16384
#define D 128
#define TEMP_INV 5.0f
#define EXP2_SCALE 7.21347520444482f   /* 5 / ln(2) */

#define BM 128
#define BN 128
#define NTILES 128                     /* colTiles per row block = N_ROWS/BN */
#define TOTAL_UNITS (NTILES * NTILES)  /* 16384 (rowTile x colTile) */
#define NCTAS 152                      /* GB300: 152 SMs */

#define SMEM_A_OFF 0
#define SMEM_B0_OFF 32768
#define SMEM_B1_OFF 65536
#define SMEM_T_OFF 98304
#define SMEM_BYTES (98304 + 1024)

// bf16 normalized vectors: rows [0,16384) = v1, rows [16384,32768) = v2
__device__ __nv_bfloat16 g_v[2 * N_ROWS * D];
__device__ float g_diag[N_ROWS];
__device__ float g_ttl[N_ROWS];

// ---------------------------------------------------------------------------
// Kernel 1: fused L2-normalize (both views) + diagonal dot + zero g_ttl/out.
// One warp per row-index n: handles emb[0][n] and emb[1][n].
// ---------------------------------------------------------------------------
__global__ void norm_kernel(const float* __restrict__ emb, float* __restrict__ out) {
    if (blockIdx.x == 0 && threadIdx.x == 0) out[0] = 0.0f;
    int warp = (blockIdx.x * blockDim.x + threadIdx.x) >> 5;
    int lane = threadIdx.x & 31;
    if (warp >= N_ROWS) return;

    float4 v1 = ((const float4*)(emb + (size_t)warp * D))[lane];
    float4 v2 = ((const float4*)(emb + (size_t)(N_ROWS + warp) * D))[lane];

    float ss1 = v1.x * v1.x + v1.y * v1.y + v1.z * v1.z + v1.w * v1.w;
    float ss2 = v2.x * v2.x + v2.y * v2.y + v2.z * v2.z + v2.w * v2.w;
    float dr  = v1.x * v2.x + v1.y * v2.y + v1.z * v2.z + v1.w * v2.w;
#pragma unroll
    for (int o = 16; o; o >>= 1) {
        ss1 += __shfl_xor_sync(0xffffffffu, ss1, o);
        ss2 += __shfl_xor_sync(0xffffffffu, ss2, o);
        dr  += __shfl_xor_sync(0xffffffffu, dr, o);
    }
    float inv1 = 1.0f / fmaxf(sqrtf(ss1), 1e-12f);
    float inv2 = 1.0f / fmaxf(sqrtf(ss2), 1e-12f);

    {
        __nv_bfloat162 p0 = __floats2bfloat162_rn(v1.x * inv1, v1.y * inv1);
        __nv_bfloat162 p1 = __floats2bfloat162_rn(v1.z * inv1, v1.w * inv1);
        uint2 u;
        u.x = *reinterpret_cast<uint32_t*>(&p0);
        u.y = *reinterpret_cast<uint32_t*>(&p1);
        ((uint2*)(g_v + (size_t)warp * D))[lane] = u;
    }
    {
        __nv_bfloat162 p0 = __floats2bfloat162_rn(v2.x * inv2, v2.y * inv2);
        __nv_bfloat162 p1 = __floats2bfloat162_rn(v2.z * inv2, v2.w * inv2);
        uint2 u;
        u.x = *reinterpret_cast<uint32_t*>(&p0);
        u.y = *reinterpret_cast<uint32_t*>(&p1);
        ((uint2*)(g_v + (size_t)(N_ROWS + warp) * D))[lane] = u;
    }
    if (lane == 0) {
        g_diag[warp] = dr * inv1 * inv2;
        g_ttl[warp] = 0.0f;
    }
}

// ---------------------------------------------------------------------------
// Kernel 2 (main): persistent 152-CTA tiled bf16 MMA GEMM, fused exp2+rowsum.
// Flattened work space: unit u = rowTile*128 + colTile, contiguous slab per
// CTA (<= 2 rowTile segments => <= 2 A reloads). Partial row sums atomicAdd
// into g_ttl. 256 threads = 8 warps (4m x 2n); warp owns 32x64 sub-tile.
// B tiles double-buffered via cp.async (v2 bf16 = 4 MB, L2-resident).
// ---------------------------------------------------------------------------
__device__ __forceinline__ float ex2f(float x) {
    float y;
    asm("ex2.approx.f32 %0, %1;" : "=f"(y) : "f"(x));
    return y;
}

__device__ __forceinline__ void cp_async16(uint32_t saddr, const void* gptr) {
    asm volatile("cp.async.cg.shared.global [%0], [%1], 16;\n"
                 :: "r"(saddr), "l"(gptr) : "memory");
}
__device__ __forceinline__ void cp_async_commit() {
    asm volatile("cp.async.commit_group;\n" ::: "memory");
}
__device__ __forceinline__ void cp_async_wait_all() {
    asm volatile("cp.async.wait_group 0;\n" ::: "memory");
}

__device__ __forceinline__ void ldsm_x4(uint32_t r[4], uint32_t addr) {
    asm volatile("ldmatrix.sync.aligned.m8n8.x4.shared.b16 {%0,%1,%2,%3}, [%4];"
                 : "=r"(r[0]), "=r"(r[1]), "=r"(r[2]), "=r"(r[3]) : "r"(addr));
}

__device__ __forceinline__ void mma16816(float c[4], const uint32_t a[4],
                                         uint32_t b0, uint32_t b1) {
    asm volatile(
        "mma.sync.aligned.m16n8k16.row.col.f32.bf16.bf16.f32 "
        "{%0,%1,%2,%3},{%4,%5,%6,%7},{%8,%9},{%0,%1,%2,%3};"
        : "+f"(c[0]), "+f"(c[1]), "+f"(c[2]), "+f"(c[3])
        : "r"(a[0]), "r"(a[1]), "r"(a[2]), "r"(a[3]), "r"(b0), "r"(b1));
}

extern "C" __global__ void __launch_bounds__(256, 1)
gemm_loss_kernel() {
    extern __shared__ char smem[];
    float* ttl2 = (float*)(smem + SMEM_T_OFF);   // [2][128]

    const int tid  = threadIdx.x;
    const int lane = tid & 31;
    const int wid  = tid >> 5;
    const int wm   = wid & 3;          // 0..3 : 32-row band
    const int wn   = wid >> 2;         // 0..1 : 64-col band

    const uint32_t smA_u  = (uint32_t)__cvta_generic_to_shared(smem + SMEM_A_OFF);
    const uint32_t smB0_u = (uint32_t)__cvta_generic_to_shared(smem + SMEM_B0_OFF);
    const uint32_t smB1_u = (uint32_t)__cvta_generic_to_shared(smem + SMEM_B1_OFF);

    // fill geometry: 256 threads cover 16 rows x 16 chunks per pass; 8 passes
    // fill a 128-row tile. XOR swizzle: chunk c stored at (c ^ (row&7)).
    const int f_r0 = tid >> 4;          // 0..15
    const int f_c  = tid & 15;          // 0..15

    // ldmatrix per-lane geometry
    const int a_row0 = wm * 32 + ((lane >> 3) & 1) * 8 + (lane & 7);  // + mi*16
    const int a_cadd = (lane >> 4) & 1;                                // k-chunk sel
    const int b_rbase = wn * 64 + ((lane >> 4) & 1) * 8 + (lane & 7);  // + nn2*16
    const int b_cadd = (lane >> 3) & 1;

    // contiguous slab of work units for this CTA
    const int u0 = (int)(((unsigned)blockIdx.x * TOTAL_UNITS) / NCTAS);
    const int u1 = (int)((((unsigned)blockIdx.x + 1u) * TOTAL_UNITS) / NCTAS);
    if (u0 >= u1) return;
    const int rt0 = u0 >> 7;
    const int rt1 = (u1 - 1) >> 7;

    for (int rt = rt0; rt <= rt1; ++rt) {
        const int c0 = (rt == rt0) ? (u0 & 127) : 0;
        const int c1 = (rt == rt1) ? (((u1 - 1) & 127) + 1) : NTILES;
        const int rowBase = rt * BM;

        // ---- prefetch A tile (rt) and first B tile (c0) into buffer 0 ----
        {
            const __nv_bfloat16* gA = g_v + (size_t)rowBase * D;
            const __nv_bfloat16* gB = g_v + (size_t)(N_ROWS + c0 * BN) * D;
#pragma unroll
            for (int i = 0; i < 8; ++i) {
                int r = f_r0 + i * 16, c = f_c;
                uint32_t sw = ((c ^ (r & 7)) << 4);
                cp_async16(smA_u + r * 256 + sw,
                           (const void*)((const uint4*)(gA + (size_t)r * D) + c));
                cp_async16(smB0_u + r * 256 + sw,
                           (const void*)((const uint4*)(gB + (size_t)r * D) + c));
            }
        }
        cp_async_commit();

        float rsum[2][2] = {{0.f, 0.f}, {0.f, 0.f}};

        for (int ct = c0; ct < c1; ++ct) {
            cp_async_wait_all();
            __syncthreads();   // buffer ready; all warps past previous compute

            const int par = (ct - c0) & 1;
            const uint32_t smB_u  = par ? smB1_u : smB0_u;
            const uint32_t smBn_u = par ? smB0_u : smB1_u;

            // issue next tile's loads into alternate buffer (overlaps compute)
            if (ct + 1 < c1) {
                const __nv_bfloat16* gB = g_v + (size_t)(N_ROWS + (ct + 1) * BN) * D;
#pragma unroll
                for (int i = 0; i < 8; ++i) {
                    int r = f_r0 + i * 16, c = f_c;
                    cp_async16(smBn_u + r * 256 + ((c ^ (r & 7)) << 4),
                               (const void*)((const uint4*)(gB + (size_t)r * D) + c));
                }
            }
            cp_async_commit();

            float acc[2][8][4];
#pragma unroll
            for (int mi = 0; mi < 2; ++mi)
#pragma unroll
                for (int nn = 0; nn < 8; ++nn)
#pragma unroll
                    for (int j = 0; j < 4; ++j) acc[mi][nn][j] = 0.0f;

#pragma unroll
            for (int kk = 0; kk < 8; ++kk) {
                uint32_t a[2][4];
#pragma unroll
                for (int mi = 0; mi < 2; ++mi) {
                    int row = a_row0 + mi * 16;
                    int chunk = (kk * 2 + a_cadd) ^ (row & 7);
                    ldsm_x4(a[mi], smA_u + row * 256 + chunk * 16);
                }
                uint32_t b[4][4];
#pragma unroll
                for (int nn2 = 0; nn2 < 4; ++nn2) {
                    int rn = b_rbase + nn2 * 16;
                    int chunk = (kk * 2 + b_cadd) ^ (rn & 7);
                    ldsm_x4(b[nn2], smB_u + rn * 256 + chunk * 16);
                }
#pragma unroll
                for (int mi = 0; mi < 2; ++mi)
#pragma unroll
                    for (int nn2 = 0; nn2 < 4; ++nn2) {
                        mma16816(acc[mi][2 * nn2 + 0], a[mi], b[nn2][0], b[nn2][1]);
                        mma16816(acc[mi][2 * nn2 + 1], a[mi], b[nn2][2], b[nn2][3]);
                    }
            }

            // ---- fused epilogue: exp(sim/T) row-sum ----
            // c0,c1 -> row (lane>>2) (hi=0); c2,c3 -> row+8 (hi=1)
#pragma unroll
            for (int mi = 0; mi < 2; ++mi)
#pragma unroll
                for (int nn = 0; nn < 8; ++nn) {
                    float e0 = ex2f(acc[mi][nn][0] * EXP2_SCALE);
                    float e1 = ex2f(acc[mi][nn][1] * EXP2_SCALE);
                    float e2 = ex2f(acc[mi][nn][2] * EXP2_SCALE);
                    float e3 = ex2f(acc[mi][nn][3] * EXP2_SCALE);
                    rsum[mi][0] += e0 + e1;
                    rsum[mi][1] += e2 + e3;
                }
        }

        // ---- reduce partial row sums and accumulate into g_ttl ----
#pragma unroll
        for (int mi = 0; mi < 2; ++mi)
#pragma unroll
            for (int hi = 0; hi < 2; ++hi) {
                float v = rsum[mi][hi];
                v += __shfl_xor_sync(0xffffffffu, v, 1);
                v += __shfl_xor_sync(0xffffffffu, v, 2);
                if ((lane & 3) == 0)
                    ttl2[wn * 128 + wm * 32 + mi * 16 + hi * 8 + (lane >> 2)] = v;
            }
        __syncthreads();

        if (wid == 0) {
#pragma unroll
            for (int i = 0; i < 4; ++i) {
                int r = lane + i * 32;
                atomicAdd(&g_ttl[rowBase + r], ttl2[r] + ttl2[128 + r]);
            }
        }
        __syncthreads();   // protect ttl2 + B buffers before next segment
    }
}

// ---------------------------------------------------------------------------
// Kernel 3: loss = sum_n ( log(ttl[n]) - 5 * diag[n] ), atomic into out.
// ---------------------------------------------------------------------------
__global__ void loss_kernel(float* __restrict__ out) {
    __shared__ float wsum[4];
    int i = blockIdx.x * blockDim.x + threadIdx.x;
    int lane = threadIdx.x & 31;
    int w = threadIdx.x >> 5;

    float local = logf(g_ttl[i]) - TEMP_INV * g_diag[i];
#pragma unroll
    for (int o = 16; o; o >>= 1) local += __shfl_xor_sync(0xffffffffu, local, o);
    if (lane == 0) wsum[w] = local;
    __syncthreads();
    if (threadIdx.x == 0) {
        float s = wsum[0] + wsum[1] + wsum[2] + wsum[3];
        atomicAdd(out, s);
    }
}

// ---------------------------------------------------------------------------
extern "C" void kernel_launch(void* const* d_in, const int* in_sizes, int n_in,
                              void* d_out, int out_size) {
    const float* emb = (const float*)d_in[0];
    float* out = (float*)d_out;

    // 16384 row-pairs, 8 warps per block
    norm_kernel<<<N_ROWS / 8, 256>>>(emb, out);

    cudaFuncSetAttribute(gemm_loss_kernel,
                         cudaFuncAttributeMaxDynamicSharedMemorySize, SMEM_BYTES);
    gemm_loss_kernel<<<NCTAS, 256, SMEM_BYTES>>>();

    loss_kernel<<<N_ROWS / 128, 128>>>(out);
}